// round 17
// baseline (speedup 1.0000x reference)
#include <cuda_runtime.h>
#include <cstdint>

#define Bq    128
#define NTREE 2047
#define DIN   512
#define NLS   64
#define MROWS (Bq * NTREE)
#define NKT   (DIN / 32)

__device__ float g_emis[(size_t)MROWS * NLS];        // 67 MB
__device__ float g_bufA[(size_t)Bq * 512 * NLS];     // 16.8 MB
__device__ float g_bufB[(size_t)Bq * 512 * NLS];     // 16.8 MB

// tf32 MMA reads only the tf32 bit-fields; raw fp32 bits == RZ truncation
// (measured rel_err 2.9e-4, gate 1e-3).
__device__ __forceinline__ uint32_t f2tf32(float f) { return __float_as_uint(f); }

__device__ __forceinline__ void mma_tf32(float c[4], const uint32_t a[4], const uint32_t b[2]) {
    asm volatile(
        "mma.sync.aligned.m16n8k8.row.col.f32.tf32.tf32.f32 "
        "{%0,%1,%2,%3}, {%4,%5,%6,%7}, {%8,%9}, {%0,%1,%2,%3};"
        : "+f"(c[0]), "+f"(c[1]), "+f"(c[2]), "+f"(c[3])
        : "r"(a[0]), "r"(a[1]), "r"(a[2]), "r"(a[3]), "r"(b[0]), "r"(b[1]));
}

__device__ __forceinline__ void cp_async16(void* smem_dst, const void* gmem_src) {
    uint32_t dst = (uint32_t)__cvta_generic_to_shared(smem_dst);
    asm volatile("cp.async.cg.shared.global [%0], [%1], 16;"
                 :: "r"(dst), "l"(gmem_src) : "memory");
}
__device__ __forceinline__ void cp_commit() {
    asm volatile("cp.async.commit_group;" ::: "memory");
}
__device__ __forceinline__ void cp_wait2() {
    asm volatile("cp.async.wait_group 2;" ::: "memory");
}
__device__ __forceinline__ void cp_wait0() {
    asm volatile("cp.async.wait_group 0;" ::: "memory");
}

// ---------------------------------------------------------------------------
// Emission GEMM: emis[M,64] = hidden[M,512] @ W[512,64] + b
// BM=128, BN=64, BK=32; 256 threads; 4-stage cp.async pipeline.
// NEW: warp tile 64x32 with 2-way in-CTA split-K (8 warps = 4 pos x 2 kgrp)
// -> LDS bytes/FLOP cut 25% (crossbar was the binder per H3 model).
// One-time smem reduction merges k-halves before the bias epilogue.
// ---------------------------------------------------------------------------
#define AS_STRIDE 36
#define BS_STRIDE 72
#define A_STAGE   (128 * AS_STRIDE)
#define B_STAGE   (32 * BS_STRIDE)
#define EMIS_SMEM ((4 * A_STAGE + 4 * B_STAGE) * 4)   // 110592 bytes
#define RED_STRIDE 65                                  // reduce scratch stride

extern __shared__ float dynsm[];

__global__ __launch_bounds__(256) void emis_kernel(
    const float* __restrict__ hidden, const float* __restrict__ W,
    const float* __restrict__ bias, float* __restrict__ emis)
{
    const int t    = threadIdx.x;
    const int wid  = t >> 5, lane = t & 31;
    const int g    = lane >> 2, tig = lane & 3;
    const int wk   = wid >> 2;            // k-group 0/1
    const int wpos = wid & 3;
    const int wm   = wpos >> 1, wn = wpos & 1;   // 2M x 2N positions
    const size_t brow = (size_t)blockIdx.x * 128;

    float* Abase = dynsm;
    float* Bbase = dynsm + 4 * A_STAGE;

    const int a_r0 = t >> 3, a_c4 = t & 7;
    const int b_r0 = t >> 4, b_c4 = t & 15;

    auto load_tiles = [&](int kt, int s) {
        const int kb = kt * 32;
        float* As = Abase + s * A_STAGE;
        float* Bs = Bbase + s * B_STAGE;
        #pragma unroll
        for (int i = 0; i < 4; i++) {
            int r = a_r0 + 32 * i;
            cp_async16(As + r * AS_STRIDE + a_c4 * 4,
                       hidden + (brow + r) * DIN + kb + a_c4 * 4);
        }
        #pragma unroll
        for (int i = 0; i < 2; i++) {
            int r = b_r0 + 16 * i;
            cp_async16(Bs + r * BS_STRIDE + b_c4 * 4,
                       W + (size_t)(kb + r) * NLS + b_c4 * 4);
        }
        cp_commit();
    };

    float acc[4][4][4];
    #pragma unroll
    for (int mi = 0; mi < 4; mi++)
        #pragma unroll
        for (int ni = 0; ni < 4; ni++)
            #pragma unroll
            for (int j = 0; j < 4; j++) acc[mi][ni][j] = 0.f;

    load_tiles(0, 0);
    load_tiles(1, 1);
    load_tiles(2, 2);

    for (int kt = 0; kt < NKT; kt++) {
        cp_wait2();
        __syncthreads();
        if (kt + 3 < NKT) load_tiles(kt + 3, (kt + 3) & 3);
        else              cp_commit();   // keep group accounting exact

        const int s = kt & 3;
        const float* As = Abase + s * A_STAGE;
        const float* Bs = Bbase + s * B_STAGE;

        #pragma unroll
        for (int kh = 0; kh < 2; kh++) {
            const int k0 = (wk * 2 + kh) * 8;   // this warp's k-slice
            uint32_t a[4][4];
            #pragma unroll
            for (int mi = 0; mi < 4; mi++) {
                const int r0 = wm * 64 + mi * 16;
                a[mi][0] = f2tf32(As[(r0 + g) * AS_STRIDE + k0 + tig]);
                a[mi][1] = f2tf32(As[(r0 + 8 + g) * AS_STRIDE + k0 + tig]);
                a[mi][2] = f2tf32(As[(r0 + g) * AS_STRIDE + k0 + tig + 4]);
                a[mi][3] = f2tf32(As[(r0 + 8 + g) * AS_STRIDE + k0 + tig + 4]);
            }
            uint32_t bf[4][2];
            #pragma unroll
            for (int ni = 0; ni < 4; ni++) {
                const int c0 = wn * 32 + ni * 8;
                bf[ni][0] = f2tf32(Bs[(k0 + tig) * BS_STRIDE + c0 + g]);
                bf[ni][1] = f2tf32(Bs[(k0 + tig + 4) * BS_STRIDE + c0 + g]);
            }
            #pragma unroll
            for (int mi = 0; mi < 4; mi++)
                #pragma unroll
                for (int ni = 0; ni < 4; ni++)
                    mma_tf32(acc[mi][ni], a[mi], bf[ni]);
        }
    }

    // ---- split-K reduction: wk=1 partials -> smem -> wk=0 adds ----
    float* red = dynsm;                      // 128*65 = 8320 floats (33 KB)
    __syncthreads();                         // k-loop smem reads done
    if (wk == 1) {
        #pragma unroll
        for (int mi = 0; mi < 4; mi++) {
            const int r0 = wm * 64 + mi * 16;
            #pragma unroll
            for (int ni = 0; ni < 4; ni++) {
                const int c0 = wn * 32 + ni * 8 + tig * 2;
                red[(r0 + g) * RED_STRIDE + c0]         = acc[mi][ni][0];
                red[(r0 + g) * RED_STRIDE + c0 + 1]     = acc[mi][ni][1];
                red[(r0 + 8 + g) * RED_STRIDE + c0]     = acc[mi][ni][2];
                red[(r0 + 8 + g) * RED_STRIDE + c0 + 1] = acc[mi][ni][3];
            }
        }
    }
    __syncthreads();

    if (wk == 0) {
        #pragma unroll
        for (int mi = 0; mi < 4; mi++) {
            const size_t r0 = brow + wm * 64 + mi * 16;
            const int rl0 = wm * 64 + mi * 16;
            #pragma unroll
            for (int ni = 0; ni < 4; ni++) {
                const int c0 = wn * 32 + ni * 8 + tig * 2;
                const float b0 = bias[c0], b1 = bias[c0 + 1];
                float s0 = acc[mi][ni][0] + red[(rl0 + g) * RED_STRIDE + c0]         + b0;
                float s1 = acc[mi][ni][1] + red[(rl0 + g) * RED_STRIDE + c0 + 1]     + b1;
                float s2 = acc[mi][ni][2] + red[(rl0 + 8 + g) * RED_STRIDE + c0]     + b0;
                float s3 = acc[mi][ni][3] + red[(rl0 + 8 + g) * RED_STRIDE + c0 + 1] + b1;
                *reinterpret_cast<float2*>(emis + (r0 + g) * NLS + c0)     = make_float2(s0, s1);
                *reinterpret_cast<float2*>(emis + (r0 + 8 + g) * NLS + c0) = make_float2(s2, s3);
            }
        }
    }
}

// ---------------------------------------------------------------------------
// Fused DOUBLE level (levels 512+256) — unchanged, passed.
// ---------------------------------------------------------------------------
#define F2_SMEM ((64 * 68 + 128 * 68 + 128) * 4)   // 52736 bytes

__global__ __launch_bounds__(256) void fused2_kernel(
    const float* __restrict__ child, size_t childStride,
    const float* __restrict__ trans,
    const float* __restrict__ emis, int midOff, int topOff,
    float* __restrict__ out, size_t outStride)
{
    float* Ts   = dynsm;
    float* Es   = dynsm + 64 * 68;
    float* mrow = dynsm + 64 * 68 + 128 * 68;

    const int t   = threadIdx.x;
    const int wid = t >> 5, lane = t & 31;
    const int g   = lane >> 2, tig = lane & 3;
    const unsigned pm = 3u << (lane & 30);
    const int b   = blockIdx.y;
    const int pbase = blockIdx.x * 32;

    const float* cb = child + (size_t)b * childStride + (size_t)pbase * 4 * 64;
    #pragma unroll
    for (int i = 0; i < 8; i++) {
        int idx = t + 256 * i;
        int r = idx >> 4, c4 = idx & 15;
        float4 v = *reinterpret_cast<const float4*>(cb + (size_t)r * 64 + c4 * 4);
        *reinterpret_cast<float4*>(&Es[r * 68 + c4 * 4]) = v;
    }

    float em[16], et[8];
    #pragma unroll
    for (int i = 0; i < 16; i++) {
        int idx = t + 256 * i;
        int p = idx >> 6, l = idx & 63;
        em[i] = emis[((size_t)b * NTREE + midOff + 2 * pbase + p) * NLS + l];
    }
    #pragma unroll
    for (int i = 0; i < 8; i++) {
        int idx = t + 256 * i;
        int q = idx >> 6, l = idx & 63;
        et[i] = emis[((size_t)b * NTREE + topOff + pbase + q) * NLS + l];
    }

    #pragma unroll
    for (int i = 0; i < 16; i++) {
        int idx = t + 256 * i;
        Ts[(idx >> 6) * 68 + (idx & 63)] = __expf(trans[idx]);
    }
    __syncthreads();

    {   // Level A maxexp: 2 threads/row x 128 rows
        const int r = t >> 1, h = t & 1;
        float* row = Es + r * 68 + h * 32;
        float m = row[0];
        #pragma unroll
        for (int k = 1; k < 32; k++) m = fmaxf(m, row[k]);
        m = fmaxf(m, __shfl_xor_sync(pm, m, 1));
        if (h == 0) mrow[r] = m;
        #pragma unroll
        for (int k = 0; k < 32; k++) row[k] = __expf(row[k] - m);
    }
    __syncthreads();

    {   // Level A MMA
        const int rm = wid * 16;
        float acc[8][4];
        #pragma unroll
        for (int ni = 0; ni < 8; ni++)
            #pragma unroll
            for (int j = 0; j < 4; j++) acc[ni][j] = 0.f;

        #pragma unroll
        for (int kk = 0; kk < 8; kk++) {
            const int k0 = kk * 8;
            uint32_t a[4];
            a[0] = f2tf32(Es[(rm + g) * 68 + k0 + tig]);
            a[1] = f2tf32(Es[(rm + 8 + g) * 68 + k0 + tig]);
            a[2] = f2tf32(Es[(rm + g) * 68 + k0 + tig + 4]);
            a[3] = f2tf32(Es[(rm + 8 + g) * 68 + k0 + tig + 4]);
            #pragma unroll
            for (int ni = 0; ni < 8; ni++) {
                uint32_t bf[2];
                bf[0] = f2tf32(Ts[(ni * 8 + g) * 68 + k0 + tig]);
                bf[1] = f2tf32(Ts[(ni * 8 + g) * 68 + k0 + tig + 4]);
                mma_tf32(acc[ni], a, bf);
            }
        }
        const float m0 = mrow[rm + g], m1 = mrow[rm + 8 + g];
        #pragma unroll
        for (int ni = 0; ni < 8; ni++) {
            const int c0 = ni * 8 + tig * 2;
            Es[(rm + g) * 68 + c0]         = m0 + __logf(acc[ni][0]);
            Es[(rm + g) * 68 + c0 + 1]     = m0 + __logf(acc[ni][1]);
            Es[(rm + 8 + g) * 68 + c0]     = m1 + __logf(acc[ni][2]);
            Es[(rm + 8 + g) * 68 + c0 + 1] = m1 + __logf(acc[ni][3]);
        }
    }
    __syncthreads();

    #pragma unroll
    for (int i = 0; i < 16; i++) {
        int idx = t + 256 * i;
        int p = idx >> 6, l = idx & 63;
        float v = em[i] + Es[(2 * p) * 68 + l] + Es[(2 * p + 1) * 68 + l];
        Es[(2 * p) * 68 + l] = v;
    }
    __syncthreads();

    if (t < 128) {
        const int r = t >> 1, h = t & 1;
        float* row = Es + (2 * r) * 68 + h * 32;
        float m = row[0];
        #pragma unroll
        for (int k = 1; k < 32; k++) m = fmaxf(m, row[k]);
        m = fmaxf(m, __shfl_xor_sync(pm, m, 1));
        if (h == 0) mrow[r] = m;
        #pragma unroll
        for (int k = 0; k < 32; k++) row[k] = __expf(row[k] - m);
    }
    __syncthreads();

    if (wid < 4) {
        const int rm = wid * 16;
        float acc[8][4];
        #pragma unroll
        for (int ni = 0; ni < 8; ni++)
            #pragma unroll
            for (int j = 0; j < 4; j++) acc[ni][j] = 0.f;

        #pragma unroll
        for (int kk = 0; kk < 8; kk++) {
            const int k0 = kk * 8;
            uint32_t a[4];
            a[0] = f2tf32(Es[(2 * (rm + g)) * 68 + k0 + tig]);
            a[1] = f2tf32(Es[(2 * (rm + 8 + g)) * 68 + k0 + tig]);
            a[2] = f2tf32(Es[(2 * (rm + g)) * 68 + k0 + tig + 4]);
            a[3] = f2tf32(Es[(2 * (rm + 8 + g)) * 68 + k0 + tig + 4]);
            #pragma unroll
            for (int ni = 0; ni < 8; ni++) {
                uint32_t bf[2];
                bf[0] = f2tf32(Ts[(ni * 8 + g) * 68 + k0 + tig]);
                bf[1] = f2tf32(Ts[(ni * 8 + g) * 68 + k0 + tig + 4]);
                mma_tf32(acc[ni], a, bf);
            }
        }
        const float m0 = mrow[rm + g], m1 = mrow[rm + 8 + g];
        #pragma unroll
        for (int ni = 0; ni < 8; ni++) {
            const int c0 = ni * 8 + tig * 2;
            Es[(2 * (rm + g)) * 68 + c0]         = m0 + __logf(acc[ni][0]);
            Es[(2 * (rm + g)) * 68 + c0 + 1]     = m0 + __logf(acc[ni][1]);
            Es[(2 * (rm + 8 + g)) * 68 + c0]     = m1 + __logf(acc[ni][2]);
            Es[(2 * (rm + 8 + g)) * 68 + c0 + 1] = m1 + __logf(acc[ni][3]);
        }
    }
    __syncthreads();

    #pragma unroll
    for (int i = 0; i < 8; i++) {
        int idx = t + 256 * i;
        int q = idx >> 6, l = idx & 63;
        out[(size_t)b * outStride + (size_t)(pbase + q) * 64 + l]
            = et[i] + Es[(4 * q) * 68 + l] + Es[(4 * q + 2) * 68 + l];
    }
}

// ---------------------------------------------------------------------------
// MEGA tail: levels nP = 128..1 in ONE kernel (unchanged from R13 design).
// ---------------------------------------------------------------------------
#define MEGA_SMEM ((64*68 + 256*68 + 128*68 + 255*64 + 256) * 4)   // 188160 B

__global__ __launch_bounds__(256) void mega_tail_kernel(
    const float* __restrict__ child, size_t childStride,   // 256 rows/batch
    const float* __restrict__ trans,
    const float* __restrict__ emis,
    float* __restrict__ out)
{
    float* Ts   = dynsm;                   // [64][68]
    float* E    = Ts + 64 * 68;            // [256][68]
    float* F    = E + 256 * 68;            // [128][68]
    float* ES   = F + 128 * 68;            // [255][64]  emis nodes 0..254
    float* mrow = ES + 255 * 64;           // [256]

    const int t    = threadIdx.x;
    const int wid  = t >> 5, lane = t & 31;
    const int g    = lane >> 2, tig = lane & 3;
    const int b    = blockIdx.x;

    const float* eb = emis + (size_t)b * NTREE * 64;
    for (int i = t; i < 4080; i += 256)
        cp_async16(ES + i * 4, eb + i * 4);
    const float* cb = child + (size_t)b * childStride;
    #pragma unroll
    for (int i = 0; i < 16; i++) {
        int idx = t + 256 * i;
        int r = idx >> 4, c4 = idx & 15;
        cp_async16(E + r * 68 + c4 * 4, cb + (size_t)r * 64 + c4 * 4);
    }
    cp_commit();

    #pragma unroll
    for (int i = 0; i < 16; i++) {
        int idx = t + 256 * i;
        Ts[(idx >> 6) * 68 + (idx & 63)] = __expf(trans[idx]);
    }
    cp_wait0();
    __syncthreads();

    float* cur = E;
    float* nxt = F;

    for (int nP = 128; nP >= 1; nP >>= 1) {
        const int nC = 2 * nP;
        int tpr = 256 / nC; if (tpr > 8) tpr = 8;      // 1,2,4,8 (pow2)
        const int sh = 31 - __clz(tpr);
        const int chunk = 64 >> sh;

        {   // max + exp: tpr threads/row; segments never span warps (tpr<=8)
            const int r = t >> sh, h = t & (tpr - 1);
            if (r < nC) {
                float* row = cur + r * 68 + h * chunk;
                float m = row[0];
                for (int k = 1; k < chunk; k++) m = fmaxf(m, row[k]);
                const unsigned base = (unsigned)(lane & ~(tpr - 1));
                const unsigned mask = ((1u << tpr) - 1u) << base;
                for (int off = 1; off < tpr; off <<= 1)
                    m = fmaxf(m, __shfl_xor_sync(mask, m, off));
                if (h == 0) mrow[r] = m;
                for (int k = 0; k < chunk; k++) row[k] = __expf(row[k] - m);
            }
        }
        __syncthreads();

        for (int tile = wid; tile * 16 < nC; tile += 8) {
            const int rm = tile * 16;
            float acc[8][4];
            #pragma unroll
            for (int ni = 0; ni < 8; ni++)
                #pragma unroll
                for (int j = 0; j < 4; j++) acc[ni][j] = 0.f;

            #pragma unroll
            for (int kk = 0; kk < 8; kk++) {
                const int k0 = kk * 8;
                uint32_t a[4];
                a[0] = f2tf32(cur[(rm + g) * 68 + k0 + tig]);
                a[1] = f2tf32(cur[(rm + 8 + g) * 68 + k0 + tig]);
                a[2] = f2tf32(cur[(rm + g) * 68 + k0 + tig + 4]);
                a[3] = f2tf32(cur[(rm + 8 + g) * 68 + k0 + tig + 4]);
                #pragma unroll
                for (int ni = 0; ni < 8; ni++) {
                    uint32_t bf[2];
                    bf[0] = f2tf32(Ts[(ni * 8 + g) * 68 + k0 + tig]);
                    bf[1] = f2tf32(Ts[(ni * 8 + g) * 68 + k0 + tig + 4]);
                    mma_tf32(acc[ni], a, bf);
                }
            }
            const float m0 = mrow[rm + g], m1 = mrow[rm + 8 + g];
            #pragma unroll
            for (int ni = 0; ni < 8; ni++) {
                const int c0 = ni * 8 + tig * 2;
                cur[(rm + g) * 68 + c0]         = m0 + __logf(acc[ni][0]);
                cur[(rm + g) * 68 + c0 + 1]     = m0 + __logf(acc[ni][1]);
                cur[(rm + 8 + g) * 68 + c0]     = m1 + __logf(acc[ni][2]);
                cur[(rm + 8 + g) * 68 + c0 + 1] = m1 + __logf(acc[ni][3]);
            }
        }
        __syncthreads();

        for (int i = t; i < nP * 64; i += 256) {
            int p = i >> 6, l = i & 63;
            float v = ES[(nP - 1 + p) * 64 + l]
                    + cur[(2 * p) * 68 + l] + cur[(2 * p + 1) * 68 + l];
            if (nP == 1) out[(size_t)b * 64 + l] = v;
            else         nxt[p * 68 + l] = v;
        }
        __syncthreads();

        float* tmp = cur; cur = nxt; nxt = tmp;
    }
}

extern "C" void kernel_launch(void* const* d_in, const int* in_sizes, int n_in,
                              void* d_out, int out_size)
{
    const float* hidden = (const float*)d_in[0];
    const float* W      = (const float*)d_in[1];
    const float* bias   = (const float*)d_in[2];
    const float* trans  = (const float*)d_in[3];
    float* out = (float*)d_out;

    float *emis, *bufA;
    cudaGetSymbolAddress((void**)&emis, g_emis);
    cudaGetSymbolAddress((void**)&bufA, g_bufA);

    cudaFuncSetAttribute(emis_kernel,
                         cudaFuncAttributeMaxDynamicSharedMemorySize, EMIS_SMEM);
    cudaFuncSetAttribute(fused2_kernel,
                         cudaFuncAttributeMaxDynamicSharedMemorySize, F2_SMEM);
    cudaFuncSetAttribute(mega_tail_kernel,
                         cudaFuncAttributeMaxDynamicSharedMemorySize, MEGA_SMEM);

    emis_kernel<<<MROWS / 128, 256, EMIS_SMEM>>>(hidden, W, bias, emis);

    const size_t bufStride = (size_t)512 * 64;

    {   // Levels 512+256 fused (grandchildren = leaves) -> bufA (256 rows/batch)
        dim3 grid(8, Bq);
        fused2_kernel<<<grid, 256, F2_SMEM>>>(
            emis + (size_t)1023 * 64, (size_t)NTREE * 64, trans,
            emis, 511, 255, bufA, bufStride);
    }
    // Levels 128..1 in one kernel
    mega_tail_kernel<<<Bq, 256, MEGA_SMEM>>>(bufA, bufStride, trans, emis, out);
}